// round 15
// baseline (speedup 1.0000x reference)
#include <cuda_runtime.h>
#include <math.h>

#define NPTS 8192
#define DIM  128
#define HID  256
#define KNN  16
#define LIST 17
#define QB   4

// Scratch (no cudaMalloc allowed)
__device__ float g_sq[NPTS];
__device__ int   g_idx[NPTS * KNN];
__device__ float g_U[NPTS * HID];   // x @ W1[0:128,:]
__device__ float g_A[NPTS * HID];   // x @ (W1[128:,:]-W1[0:128,:]) + b1

__device__ __forceinline__ float gelu_f(float v) {
    return 0.5f * v * (1.0f + erff(v * 0.7071067811865475f));
}

// ---------------------------------------------------------------------------
// Phase 0: squared norms, with rounding matching jnp.sum(pf*pf, axis=-1)
// ---------------------------------------------------------------------------
__global__ void sq_kernel(const float* __restrict__ pts) {
    int i = blockIdx.x * 256 + threadIdx.x;
    float px = pts[2 * i], py = pts[2 * i + 1];
    g_sq[i] = __fadd_rn(__fmul_rn(px, px), __fmul_rn(py, py));
}

// ---------------------------------------------------------------------------
// Phase 1: exact-order KNN (top-17 smallest d2, stable ties by lower index)
// d2 = rn(rn(s_i + s_j) - 2 * fmaf(y_i, y_j, rn(x_i * x_j)))
// ---------------------------------------------------------------------------
__global__ __launch_bounds__(256) void knn_kernel(const float* __restrict__ pts) {
    __shared__ float cx[1024], cy[1024], cs[1024];
    int i = blockIdx.x * 256 + threadIdx.x;
    float px = pts[2 * i], py = pts[2 * i + 1], ps = g_sq[i];

    float bd[LIST];
    int   bi[LIST];
    #pragma unroll
    for (int k = 0; k < LIST; ++k) { bd[k] = INFINITY; bi[k] = 0x7fffffff; }
    float wd = INFINITY; int wi = 0x7fffffff;

    for (int t0 = 0; t0 < NPTS; t0 += 1024) {
        for (int s = threadIdx.x; s < 1024; s += 256) {
            int j = t0 + s;
            cx[s] = pts[2 * j];
            cy[s] = pts[2 * j + 1];
            cs[s] = g_sq[j];
        }
        __syncthreads();
        for (int jj = 0; jj < 1024; ++jj) {
            float dot = fmaf(py, cy[jj], __fmul_rn(px, cx[jj]));
            float d2  = __fsub_rn(__fadd_rn(ps, cs[jj]), __fmul_rn(2.0f, dot));
            int   j   = t0 + jj;
            if (d2 < wd || (d2 == wd && j < wi)) {
                int p = LIST - 1;
                #pragma unroll 1
                while (p > 0 && (d2 < bd[p - 1] || (d2 == bd[p - 1] && j < bi[p - 1]))) {
                    bd[p] = bd[p - 1]; bi[p] = bi[p - 1]; --p;
                }
                bd[p] = d2; bi[p] = j;
                wd = bd[LIST - 1]; wi = bi[LIST - 1];
            }
        }
        __syncthreads();
    }
    // Drop rank 0 (self), keep ranks 1..16
    #pragma unroll
    for (int k = 0; k < KNN; ++k) g_idx[i * KNN + k] = bi[k + 1];
}

// ---------------------------------------------------------------------------
// Phase 2: U = x @ W1[0:128,:]   (z=0)
//          A = x @ (W1[128:,:]-W1[0:128,:]) + b1   (z=1)
// 64x64 tile, K=128 full, per-thread 4x4 micro-tile.
// ---------------------------------------------------------------------------
__global__ __launch_bounds__(256) void ua_kernel(const float* __restrict__ x,
                                                 const float* __restrict__ W1,
                                                 const float* __restrict__ b1) {
    __shared__ __align__(16) float ws[128 * 64];
    __shared__ float xsT[128 * 65];   // transposed, padded
    int bm = blockIdx.x * 64, bn = blockIdx.y * 64, z = blockIdx.z;
    int tid = threadIdx.x;

    for (int e = tid; e < 64 * 128; e += 256) {
        int m = e >> 7, d = e & 127;
        xsT[d * 65 + m] = x[(bm + m) * DIM + d];
    }
    for (int e = tid; e < 128 * 64; e += 256) {
        int kk = e >> 6, c = e & 63;
        int col = bn + c;
        float w = W1[kk * HID + col];
        if (z) w = W1[(128 + kk) * HID + col] - w;
        ws[kk * 64 + c] = w;
    }
    __syncthreads();

    int tx = tid & 15, ty = tid >> 4;
    float acc[4][4];
    #pragma unroll
    for (int u = 0; u < 4; ++u)
        #pragma unroll
        for (int v = 0; v < 4; ++v) acc[u][v] = 0.0f;

    #pragma unroll 4
    for (int kk = 0; kk < 128; ++kk) {
        float a0 = xsT[kk * 65 + ty * 4 + 0];
        float a1 = xsT[kk * 65 + ty * 4 + 1];
        float a2 = xsT[kk * 65 + ty * 4 + 2];
        float a3 = xsT[kk * 65 + ty * 4 + 3];
        float4 bv = *reinterpret_cast<const float4*>(&ws[kk * 64 + tx * 4]);
        acc[0][0] = fmaf(a0, bv.x, acc[0][0]); acc[0][1] = fmaf(a0, bv.y, acc[0][1]);
        acc[0][2] = fmaf(a0, bv.z, acc[0][2]); acc[0][3] = fmaf(a0, bv.w, acc[0][3]);
        acc[1][0] = fmaf(a1, bv.x, acc[1][0]); acc[1][1] = fmaf(a1, bv.y, acc[1][1]);
        acc[1][2] = fmaf(a1, bv.z, acc[1][2]); acc[1][3] = fmaf(a1, bv.w, acc[1][3]);
        acc[2][0] = fmaf(a2, bv.x, acc[2][0]); acc[2][1] = fmaf(a2, bv.y, acc[2][1]);
        acc[2][2] = fmaf(a2, bv.z, acc[2][2]); acc[2][3] = fmaf(a2, bv.w, acc[2][3]);
        acc[3][0] = fmaf(a3, bv.x, acc[3][0]); acc[3][1] = fmaf(a3, bv.y, acc[3][1]);
        acc[3][2] = fmaf(a3, bv.z, acc[3][2]); acc[3][3] = fmaf(a3, bv.w, acc[3][3]);
    }

    float* outp = z ? g_A : g_U;
    float bb0 = 0.f, bb1 = 0.f, bb2 = 0.f, bb3 = 0.f;
    if (z) {
        bb0 = b1[bn + tx * 4 + 0]; bb1 = b1[bn + tx * 4 + 1];
        bb2 = b1[bn + tx * 4 + 2]; bb3 = b1[bn + tx * 4 + 3];
    }
    #pragma unroll
    for (int u = 0; u < 4; ++u) {
        float4 o = make_float4(acc[u][0] + bb0, acc[u][1] + bb1,
                               acc[u][2] + bb2, acc[u][3] + bb3);
        *reinterpret_cast<float4*>(&outp[(bm + ty * 4 + u) * HID + bn + tx * 4]) = o;
    }
}

// ---------------------------------------------------------------------------
// Phase 3: per query i: h1[k] = gelu(U[idx[k]] + A[i]) (16x256),
//          out[i] = mean_k gelu(h1 @ W2 + b2).
// Persistent blocks, W2 resident in smem, 4 queries per iteration, 512 thr.
// ---------------------------------------------------------------------------
#define SMEM_MAIN ((32768 + 128 + 16384 + 1024 + 2048 + 64) * 4)

__global__ __launch_bounds__(512, 1) void main_kernel(const float* __restrict__ W2,
                                                      const float* __restrict__ b2,
                                                      float* __restrict__ out) {
    extern __shared__ __align__(16) float sm[];
    float* W2s = sm;                   // 256*128
    float* b2s = W2s + 32768;          // 128
    float* h1s = b2s + 128;            // 4*16*256
    float* As  = h1s + 16384;          // 4*256
    float* red = As + 1024;            // 4*4*128
    int*   jis = (int*)(red + 2048);   // 4*16

    int tid = threadIdx.x;
    for (int e = tid; e < HID * DIM; e += 512) W2s[e] = W2[e];
    if (tid < DIM) b2s[tid] = b2[tid];
    __syncthreads();

    for (int quad = blockIdx.x; quad < NPTS / QB; quad += gridDim.x) {
        int i0 = quad * QB;
        if (tid < QB * KNN) jis[tid] = g_idx[i0 * KNN + tid];
        for (int e = tid; e < QB * HID; e += 512) As[e] = g_A[i0 * HID + e];
        __syncthreads();

        // gather + first gelu
        #pragma unroll
        for (int s = 0; s < (QB * KNN * HID) / 512; ++s) {
            int e  = tid + 512 * s;
            int q  = e >> 12;
            int k  = (e >> 8) & 15;
            int kk = e & 255;
            int j  = jis[q * KNN + k];
            float v = g_U[j * HID + kk] + As[q * HID + kk];
            h1s[(q * KNN + k) * HID + kk] = gelu_f(v);
        }
        __syncthreads();

        // GEMM2: each thread: 4 neighbor-rows x 4 output-cols of one query
        int q  = tid >> 7;
        int kq = (tid >> 5) & 3;
        int cq = tid & 31;
        const float* hp = h1s + (q * KNN + kq * 4) * HID;

        float acc00 = 0.f, acc01 = 0.f, acc02 = 0.f, acc03 = 0.f;
        float acc10 = 0.f, acc11 = 0.f, acc12 = 0.f, acc13 = 0.f;
        float acc20 = 0.f, acc21 = 0.f, acc22 = 0.f, acc23 = 0.f;
        float acc30 = 0.f, acc31 = 0.f, acc32 = 0.f, acc33 = 0.f;

        #pragma unroll 4
        for (int kk = 0; kk < HID; ++kk) {
            float a0 = hp[kk];
            float a1 = hp[HID + kk];
            float a2 = hp[2 * HID + kk];
            float a3 = hp[3 * HID + kk];
            float4 bv = *reinterpret_cast<const float4*>(&W2s[kk * DIM + cq * 4]);
            acc00 = fmaf(a0, bv.x, acc00); acc01 = fmaf(a0, bv.y, acc01);
            acc02 = fmaf(a0, bv.z, acc02); acc03 = fmaf(a0, bv.w, acc03);
            acc10 = fmaf(a1, bv.x, acc10); acc11 = fmaf(a1, bv.y, acc11);
            acc12 = fmaf(a1, bv.z, acc12); acc13 = fmaf(a1, bv.w, acc13);
            acc20 = fmaf(a2, bv.x, acc20); acc21 = fmaf(a2, bv.y, acc21);
            acc22 = fmaf(a2, bv.z, acc22); acc23 = fmaf(a2, bv.w, acc23);
            acc30 = fmaf(a3, bv.x, acc30); acc31 = fmaf(a3, bv.y, acc31);
            acc32 = fmaf(a3, bv.z, acc32); acc33 = fmaf(a3, bv.w, acc33);
        }

        // second gelu + partial sum over this thread's 4 neighbor rows
        float bb0 = b2s[cq * 4 + 0], bb1 = b2s[cq * 4 + 1];
        float bb2 = b2s[cq * 4 + 2], bb3 = b2s[cq * 4 + 3];
        float s0 = gelu_f(acc00 + bb0) + gelu_f(acc10 + bb0) + gelu_f(acc20 + bb0) + gelu_f(acc30 + bb0);
        float s1 = gelu_f(acc01 + bb1) + gelu_f(acc11 + bb1) + gelu_f(acc21 + bb1) + gelu_f(acc31 + bb1);
        float s2 = gelu_f(acc02 + bb2) + gelu_f(acc12 + bb2) + gelu_f(acc22 + bb2) + gelu_f(acc32 + bb2);
        float s3 = gelu_f(acc03 + bb3) + gelu_f(acc13 + bb3) + gelu_f(acc23 + bb3) + gelu_f(acc33 + bb3);
        float* rp = red + (q * 4 + kq) * DIM + cq * 4;
        rp[0] = s0; rp[1] = s1; rp[2] = s2; rp[3] = s3;
        __syncthreads();

        // deterministic reduction over the 4 kq partials, write output
        {
            int qq = tid >> 7;
            int c  = tid & 127;
            const float* rr = red + qq * 4 * DIM;
            float r = ((rr[c] + rr[DIM + c]) + rr[2 * DIM + c]) + rr[3 * DIM + c];
            out[(i0 + qq) * DIM + c] = r * 0.0625f;   // mean over K=16
        }
        __syncthreads();
    }
}

// ---------------------------------------------------------------------------
extern "C" void kernel_launch(void* const* d_in, const int* in_sizes, int n_in,
                              void* d_out, int out_size) {
    (void)in_sizes; (void)n_in; (void)out_size;
    const float* x   = (const float*)d_in[0];
    const float* pts = (const float*)d_in[1];
    const float* W1  = (const float*)d_in[2];
    const float* b1  = (const float*)d_in[3];
    const float* W2  = (const float*)d_in[4];
    const float* b2  = (const float*)d_in[5];
    // d_in[6] is K = 16 (fixed for this problem)
    float* out = (float*)d_out;

    sq_kernel<<<NPTS / 256, 256>>>(pts);
    knn_kernel<<<NPTS / 256, 256>>>(pts);
    ua_kernel<<<dim3(NPTS / 64, HID / 64, 2), 256>>>(x, W1, b1);

    cudaFuncSetAttribute(main_kernel, cudaFuncAttributeMaxDynamicSharedMemorySize, SMEM_MAIN);
    main_kernel<<<304, 512, SMEM_MAIN>>>(W2, b2, out);
}

// round 16
// speedup vs baseline: 1.0024x; 1.0024x over previous
#include <cuda_runtime.h>
#include <math.h>

#define NPTS 8192
#define DIM  128
#define HID  256
#define KNN  16
#define LIST 17
#define QB   4

// Scratch (no cudaMalloc allowed)
__device__ float g_sq[NPTS];
__device__ int   g_idx[NPTS * KNN];
__device__ float g_U[NPTS * HID];   // x @ W1[0:128,:]
__device__ float g_A[NPTS * HID];   // x @ (W1[128:,:]-W1[0:128,:]) + b1

__device__ __forceinline__ float gelu_f(float v) {
    return 0.5f * v * (1.0f + erff(v * 0.7071067811865475f));
}

// ---------------------------------------------------------------------------
// Phase 0: squared norms, with rounding matching jnp.sum(pf*pf, axis=-1)
// ---------------------------------------------------------------------------
__global__ void sq_kernel(const float* __restrict__ pts) {
    int i = blockIdx.x * 256 + threadIdx.x;
    float px = pts[2 * i], py = pts[2 * i + 1];
    g_sq[i] = __fadd_rn(__fmul_rn(px, px), __fmul_rn(py, py));
}

// ---------------------------------------------------------------------------
// Phase 1: exact-order KNN (top-17 smallest d2, stable ties by lower index)
// d2 = rn(rn(s_i + s_j) - 2 * fmaf(y_i, y_j, rn(x_i * x_j)))
// ---------------------------------------------------------------------------
__global__ __launch_bounds__(256) void knn_kernel(const float* __restrict__ pts) {
    __shared__ float cx[1024], cy[1024], cs[1024];
    int i = blockIdx.x * 256 + threadIdx.x;
    float px = pts[2 * i], py = pts[2 * i + 1], ps = g_sq[i];

    float bd[LIST];
    int   bi[LIST];
    #pragma unroll
    for (int k = 0; k < LIST; ++k) { bd[k] = INFINITY; bi[k] = 0x7fffffff; }
    float wd = INFINITY; int wi = 0x7fffffff;

    for (int t0 = 0; t0 < NPTS; t0 += 1024) {
        for (int s = threadIdx.x; s < 1024; s += 256) {
            int j = t0 + s;
            cx[s] = pts[2 * j];
            cy[s] = pts[2 * j + 1];
            cs[s] = g_sq[j];
        }
        __syncthreads();
        for (int jj = 0; jj < 1024; ++jj) {
            float dot = fmaf(py, cy[jj], __fmul_rn(px, cx[jj]));
            float d2  = __fsub_rn(__fadd_rn(ps, cs[jj]), __fmul_rn(2.0f, dot));
            int   j   = t0 + jj;
            if (d2 < wd || (d2 == wd && j < wi)) {
                int p = LIST - 1;
                #pragma unroll 1
                while (p > 0 && (d2 < bd[p - 1] || (d2 == bd[p - 1] && j < bi[p - 1]))) {
                    bd[p] = bd[p - 1]; bi[p] = bi[p - 1]; --p;
                }
                bd[p] = d2; bi[p] = j;
                wd = bd[LIST - 1]; wi = bi[LIST - 1];
            }
        }
        __syncthreads();
    }
    // Drop rank 0 (self), keep ranks 1..16
    #pragma unroll
    for (int k = 0; k < KNN; ++k) g_idx[i * KNN + k] = bi[k + 1];
}

// ---------------------------------------------------------------------------
// Phase 2: U = x @ W1[0:128,:]   (z=0)
//          A = x @ (W1[128:,:]-W1[0:128,:]) + b1   (z=1)
// 64x64 tile, K=128 full, per-thread 4x4 micro-tile.
// ---------------------------------------------------------------------------
__global__ __launch_bounds__(256) void ua_kernel(const float* __restrict__ x,
                                                 const float* __restrict__ W1,
                                                 const float* __restrict__ b1) {
    __shared__ __align__(16) float ws[128 * 64];
    __shared__ float xsT[128 * 65];   // transposed, padded
    int bm = blockIdx.x * 64, bn = blockIdx.y * 64, z = blockIdx.z;
    int tid = threadIdx.x;

    for (int e = tid; e < 64 * 128; e += 256) {
        int m = e >> 7, d = e & 127;
        xsT[d * 65 + m] = x[(bm + m) * DIM + d];
    }
    for (int e = tid; e < 128 * 64; e += 256) {
        int kk = e >> 6, c = e & 63;
        int col = bn + c;
        float w = W1[kk * HID + col];
        if (z) w = W1[(128 + kk) * HID + col] - w;
        ws[kk * 64 + c] = w;
    }
    __syncthreads();

    int tx = tid & 15, ty = tid >> 4;
    float acc[4][4];
    #pragma unroll
    for (int u = 0; u < 4; ++u)
        #pragma unroll
        for (int v = 0; v < 4; ++v) acc[u][v] = 0.0f;

    #pragma unroll 4
    for (int kk = 0; kk < 128; ++kk) {
        float a0 = xsT[kk * 65 + ty * 4 + 0];
        float a1 = xsT[kk * 65 + ty * 4 + 1];
        float a2 = xsT[kk * 65 + ty * 4 + 2];
        float a3 = xsT[kk * 65 + ty * 4 + 3];
        float4 bv = *reinterpret_cast<const float4*>(&ws[kk * 64 + tx * 4]);
        acc[0][0] = fmaf(a0, bv.x, acc[0][0]); acc[0][1] = fmaf(a0, bv.y, acc[0][1]);
        acc[0][2] = fmaf(a0, bv.z, acc[0][2]); acc[0][3] = fmaf(a0, bv.w, acc[0][3]);
        acc[1][0] = fmaf(a1, bv.x, acc[1][0]); acc[1][1] = fmaf(a1, bv.y, acc[1][1]);
        acc[1][2] = fmaf(a1, bv.z, acc[1][2]); acc[1][3] = fmaf(a1, bv.w, acc[1][3]);
        acc[2][0] = fmaf(a2, bv.x, acc[2][0]); acc[2][1] = fmaf(a2, bv.y, acc[2][1]);
        acc[2][2] = fmaf(a2, bv.z, acc[2][2]); acc[2][3] = fmaf(a2, bv.w, acc[2][3]);
        acc[3][0] = fmaf(a3, bv.x, acc[3][0]); acc[3][1] = fmaf(a3, bv.y, acc[3][1]);
        acc[3][2] = fmaf(a3, bv.z, acc[3][2]); acc[3][3] = fmaf(a3, bv.w, acc[3][3]);
    }

    float* outp = z ? g_A : g_U;
    float bb0 = 0.f, bb1 = 0.f, bb2 = 0.f, bb3 = 0.f;
    if (z) {
        bb0 = b1[bn + tx * 4 + 0]; bb1 = b1[bn + tx * 4 + 1];
        bb2 = b1[bn + tx * 4 + 2]; bb3 = b1[bn + tx * 4 + 3];
    }
    #pragma unroll
    for (int u = 0; u < 4; ++u) {
        float4 o = make_float4(acc[u][0] + bb0, acc[u][1] + bb1,
                               acc[u][2] + bb2, acc[u][3] + bb3);
        *reinterpret_cast<float4*>(&outp[(bm + ty * 4 + u) * HID + bn + tx * 4]) = o;
    }
}

// ---------------------------------------------------------------------------
// Phase 3: per query i: h1[k] = gelu(U[idx[k]] + A[i]) (16x256),
//          out[i] = mean_k gelu(h1 @ W2 + b2).
// Persistent blocks, W2 resident in smem, 4 queries per iteration, 512 thr.
// ---------------------------------------------------------------------------
#define SMEM_MAIN ((32768 + 128 + 16384 + 1024 + 2048 + 64) * 4)

__global__ __launch_bounds__(512, 1) void main_kernel(const float* __restrict__ W2,
                                                      const float* __restrict__ b2,
                                                      float* __restrict__ out) {
    extern __shared__ __align__(16) float sm[];
    float* W2s = sm;                   // 256*128
    float* b2s = W2s + 32768;          // 128
    float* h1s = b2s + 128;            // 4*16*256
    float* As  = h1s + 16384;          // 4*256
    float* red = As + 1024;            // 4*4*128
    int*   jis = (int*)(red + 2048);   // 4*16

    int tid = threadIdx.x;
    for (int e = tid; e < HID * DIM; e += 512) W2s[e] = W2[e];
    if (tid < DIM) b2s[tid] = b2[tid];
    __syncthreads();

    for (int quad = blockIdx.x; quad < NPTS / QB; quad += gridDim.x) {
        int i0 = quad * QB;
        if (tid < QB * KNN) jis[tid] = g_idx[i0 * KNN + tid];
        for (int e = tid; e < QB * HID; e += 512) As[e] = g_A[i0 * HID + e];
        __syncthreads();

        // gather + first gelu
        #pragma unroll
        for (int s = 0; s < (QB * KNN * HID) / 512; ++s) {
            int e  = tid + 512 * s;
            int q  = e >> 12;
            int k  = (e >> 8) & 15;
            int kk = e & 255;
            int j  = jis[q * KNN + k];
            float v = g_U[j * HID + kk] + As[q * HID + kk];
            h1s[(q * KNN + k) * HID + kk] = gelu_f(v);
        }
        __syncthreads();

        // GEMM2: each thread: 4 neighbor-rows x 4 output-cols of one query
        int q  = tid >> 7;
        int kq = (tid >> 5) & 3;
        int cq = tid & 31;
        const float* hp = h1s + (q * KNN + kq * 4) * HID;

        float acc00 = 0.f, acc01 = 0.f, acc02 = 0.f, acc03 = 0.f;
        float acc10 = 0.f, acc11 = 0.f, acc12 = 0.f, acc13 = 0.f;
        float acc20 = 0.f, acc21 = 0.f, acc22 = 0.f, acc23 = 0.f;
        float acc30 = 0.f, acc31 = 0.f, acc32 = 0.f, acc33 = 0.f;

        #pragma unroll 4
        for (int kk = 0; kk < HID; ++kk) {
            float a0 = hp[kk];
            float a1 = hp[HID + kk];
            float a2 = hp[2 * HID + kk];
            float a3 = hp[3 * HID + kk];
            float4 bv = *reinterpret_cast<const float4*>(&W2s[kk * DIM + cq * 4]);
            acc00 = fmaf(a0, bv.x, acc00); acc01 = fmaf(a0, bv.y, acc01);
            acc02 = fmaf(a0, bv.z, acc02); acc03 = fmaf(a0, bv.w, acc03);
            acc10 = fmaf(a1, bv.x, acc10); acc11 = fmaf(a1, bv.y, acc11);
            acc12 = fmaf(a1, bv.z, acc12); acc13 = fmaf(a1, bv.w, acc13);
            acc20 = fmaf(a2, bv.x, acc20); acc21 = fmaf(a2, bv.y, acc21);
            acc22 = fmaf(a2, bv.z, acc22); acc23 = fmaf(a2, bv.w, acc23);
            acc30 = fmaf(a3, bv.x, acc30); acc31 = fmaf(a3, bv.y, acc31);
            acc32 = fmaf(a3, bv.z, acc32); acc33 = fmaf(a3, bv.w, acc33);
        }

        // second gelu + partial sum over this thread's 4 neighbor rows
        float bb0 = b2s[cq * 4 + 0], bb1 = b2s[cq * 4 + 1];
        float bb2 = b2s[cq * 4 + 2], bb3 = b2s[cq * 4 + 3];
        float s0 = gelu_f(acc00 + bb0) + gelu_f(acc10 + bb0) + gelu_f(acc20 + bb0) + gelu_f(acc30 + bb0);
        float s1 = gelu_f(acc01 + bb1) + gelu_f(acc11 + bb1) + gelu_f(acc21 + bb1) + gelu_f(acc31 + bb1);
        float s2 = gelu_f(acc02 + bb2) + gelu_f(acc12 + bb2) + gelu_f(acc22 + bb2) + gelu_f(acc32 + bb2);
        float s3 = gelu_f(acc03 + bb3) + gelu_f(acc13 + bb3) + gelu_f(acc23 + bb3) + gelu_f(acc33 + bb3);
        float* rp = red + (q * 4 + kq) * DIM + cq * 4;
        rp[0] = s0; rp[1] = s1; rp[2] = s2; rp[3] = s3;
        __syncthreads();

        // deterministic reduction over the 4 kq partials, write output
        {
            int qq = tid >> 7;
            int c  = tid & 127;
            const float* rr = red + qq * 4 * DIM;
            float r = ((rr[c] + rr[DIM + c]) + rr[2 * DIM + c]) + rr[3 * DIM + c];
            out[(i0 + qq) * DIM + c] = r * 0.0625f;   // mean over K=16
        }
        __syncthreads();
    }
}

// ---------------------------------------------------------------------------
extern "C" void kernel_launch(void* const* d_in, const int* in_sizes, int n_in,
                              void* d_out, int out_size) {
    (void)in_sizes; (void)n_in; (void)out_size;
    const float* x   = (const float*)d_in[0];
    const float* pts = (const float*)d_in[1];
    const float* W1  = (const float*)d_in[2];
    const float* b1  = (const float*)d_in[3];
    const float* W2  = (const float*)d_in[4];
    const float* b2  = (const float*)d_in[5];
    // d_in[6] is K = 16 (fixed for this problem)
    float* out = (float*)d_out;

    sq_kernel<<<NPTS / 256, 256>>>(pts);
    knn_kernel<<<NPTS / 256, 256>>>(pts);
    ua_kernel<<<dim3(NPTS / 64, HID / 64, 2), 256>>>(x, W1, b1);

    cudaFuncSetAttribute(main_kernel, cudaFuncAttributeMaxDynamicSharedMemorySize, SMEM_MAIN);
    main_kernel<<<304, 512, SMEM_MAIN>>>(W2, b2, out);
}